// round 4
// baseline (speedup 1.0000x reference)
#include <cuda_runtime.h>
#include <stdint.h>

// Problem shape (fixed by the dataset)
#define M_DIM 1024
#define K_DIM 2048
#define N_DIM 2048

// Tiling: 64 x 32 output tile per CTA, 256 threads (8 warps).
// Each warp: 8 m-rows x 32 n-lanes, acc[8] per thread.
#define BM 64
#define BN 32
#define KT 64
#define S_STRIDE 80   // 64 + 16 pad: 16B-aligned rows, conflict-free LDS.128

#define SMEM_BYTES (65536 + BM * S_STRIDE + BN * S_STRIDE)  // 73216 -> occ 2

// Scratch: quantized codes (allocation-free __device__ globals)
__device__ uint8_t g_A8[M_DIM * K_DIM];
__device__ uint8_t g_W8[N_DIM * K_DIM];
__device__ uint8_t g_LUT8[65536];

static __device__ __forceinline__ uint8_t clamp_u8(float v) {
    int c = (int)v;
    c = c < 0 ? 0 : (c > 255 ? 255 : c);
    return (uint8_t)c;
}

__global__ void quantA_kernel(const float* __restrict__ src) {
    int i = blockIdx.x * blockDim.x + threadIdx.x;   // groups of 4
    if (i < M_DIM * K_DIM / 4) {
        float4 v = ((const float4*)src)[i];
        uchar4 b;
        b.x = clamp_u8(v.x); b.y = clamp_u8(v.y);
        b.z = clamp_u8(v.z); b.w = clamp_u8(v.w);
        ((uchar4*)g_A8)[i] = b;
    }
}

__global__ void quantW_kernel(const float* __restrict__ src) {
    int i = blockIdx.x * blockDim.x + threadIdx.x;
    if (i < N_DIM * K_DIM / 4) {
        float4 v = ((const float4*)src)[i];
        uchar4 b;
        b.x = clamp_u8(v.x); b.y = clamp_u8(v.y);
        b.z = clamp_u8(v.z); b.w = clamp_u8(v.w);
        ((uchar4*)g_W8)[i] = b;
    }
}

__global__ void quantLUT_kernel(const int* __restrict__ lut) {
    int i = blockIdx.x * blockDim.x + threadIdx.x;   // groups of 4
    if (i < 65536 / 4) {
        int4 v = ((const int4*)lut)[i];
        uchar4 b;
        b.x = (uint8_t)v.x; b.y = (uint8_t)v.y;
        b.z = (uint8_t)v.z; b.w = (uint8_t)v.w;
        ((uchar4*)g_LUT8)[i] = b;
    }
}

// Index build: ((aword shift)&0xFF00)|w  -> SHF+LOP3 per index.
#define GATHER4(accv, aword, wv0, wv1, wv2, wv3)             \
    do {                                                     \
        uint32_t _i0 = (((aword) << 8)  & 0xFF00u) | (wv0);  \
        uint32_t _i1 = (( aword)        & 0xFF00u) | (wv1);  \
        uint32_t _i2 = (((aword) >> 8)  & 0xFF00u) | (wv2);  \
        uint32_t _i3 = (((aword) >> 16) & 0xFF00u) | (wv3);  \
        accv += sLUT[_i0];                                   \
        accv += sLUT[_i1];                                   \
        accv += sLUT[_i2];                                   \
        accv += sLUT[_i3];                                   \
    } while (0)

// Main LUT-GEMM kernel.
// Grid: 1024 CTAs (16 m-tiles x 64 n-tiles), 256 threads, occ 2 -> 16 warps/SM.
__global__ void __launch_bounds__(256, 2)
lut_gemm_kernel(const float* __restrict__ bias,
                float* __restrict__ out) {
    extern __shared__ uint8_t smem[];
    uint8_t* sLUT = smem;                         // 65536 B
    uint8_t* sA   = smem + 65536;                 // BM * S_STRIDE
    uint8_t* sW   = sA + BM * S_STRIDE;           // BN * S_STRIDE

    const int tid  = threadIdx.x;
    const int lane = tid & 31;
    const int warp = tid >> 5;   // 0..7 -> m-group of 8 rows

    // Copy pre-quantized LUT (64KB) into shared with 16B vector loads.
    for (int i = tid; i < 65536 / 16; i += 256) {
        ((uint4*)sLUT)[i] = ((const uint4*)g_LUT8)[i];
    }

    const int tileId = blockIdx.x;
    const int m0 = (tileId >> 6) * BM;   // 16 tile rows
    const int n0 = (tileId & 63) * BN;   // 64 tile cols

    const int mBase = warp * 8;          // warp's first row within tile
    const int nLane = n0 + lane;         // this lane's output column

    int acc[8];
#pragma unroll
    for (int i = 0; i < 8; i++) acc[i] = 0;

    const uint8_t* gA = g_A8 + (size_t)m0 * K_DIM;
    const uint8_t* gW = g_W8 + (size_t)n0 * K_DIM;

    const uint8_t* sWrow = sW + lane * S_STRIDE;   // lane*80 is 16B-aligned
    const uint8_t* sArow = sA + mBase * S_STRIDE;

    for (int k0 = 0; k0 < K_DIM; k0 += KT) {
        __syncthreads();  // previous-tile reads done (also orders LUT copy on iter 0)

        // Stage A tile: BM rows x KT bytes (u32 words). 1024 words / 256 thr.
        for (int i = tid; i < BM * (KT / 4); i += 256) {
            int m  = i >> 4;       // / (KT/4)
            int kw = i & 15;
            uint32_t v = *(const uint32_t*)(gA + (size_t)m * K_DIM + k0 + kw * 4);
            *(uint32_t*)(sA + m * S_STRIDE + kw * 4) = v;
        }
        // Stage W tile: BN rows x KT bytes. 512 words / 256 thr.
        for (int i = tid; i < BN * (KT / 4); i += 256) {
            int nn = i >> 4;
            int kw = i & 15;
            uint32_t v = *(const uint32_t*)(gW + (size_t)nn * K_DIM + k0 + kw * 4);
            *(uint32_t*)(sW + nn * S_STRIDE + kw * 4) = v;
        }
        __syncthreads();

#pragma unroll 1
        for (int kk = 0; kk < KT; kk += 16) {
            // per-lane w codes for 16 consecutive k (one LDS.128 = 4 wavefronts)
            uint4 wv = *(const uint4*)(sWrow + kk);
            uint32_t w0  =  wv.x        & 255u, w1  = (wv.x >> 8) & 255u;
            uint32_t w2  = (wv.x >> 16) & 255u, w3  =  wv.x >> 24;
            uint32_t w4  =  wv.y        & 255u, w5  = (wv.y >> 8) & 255u;
            uint32_t w6  = (wv.y >> 16) & 255u, w7  =  wv.y >> 24;
            uint32_t w8  =  wv.z        & 255u, w9  = (wv.z >> 8) & 255u;
            uint32_t w10 = (wv.z >> 16) & 255u, w11 =  wv.z >> 24;
            uint32_t w12 =  wv.w        & 255u, w13 = (wv.w >> 8) & 255u;
            uint32_t w14 = (wv.w >> 16) & 255u, w15 =  wv.w >> 24;

#pragma unroll
            for (int m = 0; m < 8; m++) {
                // warp-uniform a codes for 16 consecutive k: one broadcast
                // LDS.128 (single wavefront).
                uint4 av = *(const uint4*)(sArow + m * S_STRIDE + kk);
                GATHER4(acc[m], av.x, w0,  w1,  w2,  w3);
                GATHER4(acc[m], av.y, w4,  w5,  w6,  w7);
                GATHER4(acc[m], av.z, w8,  w9,  w10, w11);
                GATHER4(acc[m], av.w, w12, w13, w14, w15);
            }
        }
    }

    const float b = bias[nLane];
#pragma unroll
    for (int m = 0; m < 8; m++) {
        out[(size_t)(m0 + mBase + m) * N_DIM + nLane] = (float)acc[m] + b;
    }
}

extern "C" void kernel_launch(void* const* d_in, const int* in_sizes, int n_in,
                              void* d_out, int out_size) {
    const float* input  = (const float*)d_in[0];  // [M, K] codes as f32
    const float* weight = (const float*)d_in[1];  // [N, K] codes as f32
    const float* bias   = (const float*)d_in[2];  // [N]
    const int*   lut    = (const int*)d_in[3];    // [256*256]
    float* out = (float*)d_out;

    (void)in_sizes; (void)n_in; (void)out_size;

    // Opt-in to >48KB dynamic smem (idempotent; capture-safe)
    cudaFuncSetAttribute((const void*)lut_gemm_kernel,
                         cudaFuncAttributeMaxDynamicSharedMemorySize, SMEM_BYTES);

    quantA_kernel<<<(M_DIM * K_DIM / 4 + 255) / 256, 256>>>(input);
    quantW_kernel<<<(N_DIM * K_DIM / 4 + 255) / 256, 256>>>(weight);
    quantLUT_kernel<<<(65536 / 4 + 255) / 256, 256>>>(lut);

    dim3 grid(1024);  // 16 x 64 tiles of 64 x 32
    lut_gemm_kernel<<<grid, 256, SMEM_BYTES>>>(bias, out);
}

// round 6
// speedup vs baseline: 1.0137x; 1.0137x over previous
#include <cuda_runtime.h>
#include <stdint.h>

// Problem shape (fixed by the dataset)
#define M_DIM 1024
#define K_DIM 2048
#define N_DIM 2048

// Tiling: 64 x 32 output tile per CTA, 128 threads (4 warps).
// Each warp: 16 m-rows x 32 n-lanes, acc[16] per thread.
// KT=32 k-slice, double-buffered A staging; W codes live in registers.
#define BM 64
#define BN 32
#define KT 32
#define NT (K_DIM / KT)      // 64 k-tiles
#define SA_STRIDE 48         // 32 data + 16 pad; 16B-aligned rows
#define SA_BUF (BM * SA_STRIDE)          // 3072 B per buffer

#define SMEM_BYTES (65536 + 2 * SA_BUF)  // 71680 -> occ 3 (215KB/SM)

// Scratch: quantized codes (allocation-free __device__ globals)
__device__ uint8_t g_A8[M_DIM * K_DIM];
__device__ uint8_t g_W8[N_DIM * K_DIM];
__device__ uint8_t g_LUT8[65536];

static __device__ __forceinline__ uint8_t clamp_u8(float v) {
    int c = (int)v;
    c = c < 0 ? 0 : (c > 255 ? 255 : c);
    return (uint8_t)c;
}

__global__ void quantA_kernel(const float* __restrict__ src) {
    int i = blockIdx.x * blockDim.x + threadIdx.x;   // groups of 4
    if (i < M_DIM * K_DIM / 4) {
        float4 v = ((const float4*)src)[i];
        uchar4 b;
        b.x = clamp_u8(v.x); b.y = clamp_u8(v.y);
        b.z = clamp_u8(v.z); b.w = clamp_u8(v.w);
        ((uchar4*)g_A8)[i] = b;
    }
}

__global__ void quantW_kernel(const float* __restrict__ src) {
    int i = blockIdx.x * blockDim.x + threadIdx.x;
    if (i < N_DIM * K_DIM / 4) {
        float4 v = ((const float4*)src)[i];
        uchar4 b;
        b.x = clamp_u8(v.x); b.y = clamp_u8(v.y);
        b.z = clamp_u8(v.z); b.w = clamp_u8(v.w);
        ((uchar4*)g_W8)[i] = b;
    }
}

__global__ void quantLUT_kernel(const int* __restrict__ lut) {
    int i = blockIdx.x * blockDim.x + threadIdx.x;   // groups of 4
    if (i < 65536 / 4) {
        int4 v = ((const int4*)lut)[i];
        uchar4 b;
        b.x = (uint8_t)v.x; b.y = (uint8_t)v.y;
        b.z = (uint8_t)v.z; b.w = (uint8_t)v.w;
        ((uchar4*)g_LUT8)[i] = b;
    }
}

// Index build: ((aword shift)&0xFF00)|w  -> SHF+LOP3 per index.
#define GATHER4(accv, aword, wv0, wv1, wv2, wv3)             \
    do {                                                     \
        uint32_t _i0 = (((aword) << 8)  & 0xFF00u) | (wv0);  \
        uint32_t _i1 = (( aword)        & 0xFF00u) | (wv1);  \
        uint32_t _i2 = (((aword) >> 8)  & 0xFF00u) | (wv2);  \
        uint32_t _i3 = (((aword) >> 16) & 0xFF00u) | (wv3);  \
        accv += sLUT[_i0];                                   \
        accv += sLUT[_i1];                                   \
        accv += sLUT[_i2];                                   \
        accv += sLUT[_i3];                                   \
    } while (0)

// One k-group of 8: a codes from two broadcast words, w codes from two words.
#define KGROUP8(alo, ahi, wlo, whi, accv)                                  \
    do {                                                                   \
        uint32_t _w0 =  (wlo)        & 255u, _w1 = ((wlo) >> 8)  & 255u;   \
        uint32_t _w2 = ((wlo) >> 16) & 255u, _w3 =  (wlo) >> 24;           \
        uint32_t _w4 =  (whi)        & 255u, _w5 = ((whi) >> 8)  & 255u;   \
        uint32_t _w6 = ((whi) >> 16) & 255u, _w7 =  (whi) >> 24;           \
        GATHER4(accv, alo, _w0, _w1, _w2, _w3);                            \
        GATHER4(accv, ahi, _w4, _w5, _w6, _w7);                            \
    } while (0)

// Main LUT-GEMM kernel.
// Grid: 1024 CTAs (16 m-tiles x 64 n-tiles), 128 threads, occ 3 -> 12 warps/SM.
__global__ void __launch_bounds__(128, 3)
lut_gemm_kernel(const float* __restrict__ bias,
                float* __restrict__ out) {
    extern __shared__ uint8_t smem[];
    uint8_t* sLUT = smem;                 // 65536 B
    uint8_t* sA   = smem + 65536;         // [2][BM][SA_STRIDE]

    const int tid  = threadIdx.x;
    const int lane = tid & 31;
    const int warp = tid >> 5;            // 0..3 -> m-group of 16 rows

    // Copy pre-quantized LUT (64KB) into shared with 16B vector loads.
    for (int i = tid; i < 65536 / 16; i += 128) {
        ((uint4*)sLUT)[i] = ((const uint4*)g_LUT8)[i];
    }

    const int tileId = blockIdx.x;
    const int m0 = (tileId >> 6) * BM;    // 16 tile rows
    const int n0 = (tileId & 63) * BN;    // 64 tile cols

    const int mBase = warp * 16;          // warp's first row within tile
    const int nLane = n0 + lane;          // this lane's output column

    int acc[16];
#pragma unroll
    for (int i = 0; i < 16; i++) acc[i] = 0;

    // A staging: one uint4 per thread per tile. 128 threads cover 64 rows x 2 chunks.
    const int srow   = tid >> 1;
    const int schunk = (tid & 1) * 16;
    const uint8_t* gArow = g_A8 + ((size_t)(m0 + srow)) * K_DIM + schunk;
    uint8_t*       sAst  = sA + srow * SA_STRIDE + schunk;

    // W codes: this lane's private row, read straight from GMEM (L2-resident).
    const uint8_t* gWrow = g_W8 + (size_t)nLane * K_DIM;

    const uint8_t* sArow = sA + mBase * SA_STRIDE;

    // ---- prologue: tile 0 ----
    uint4 wc0 = *(const uint4*)(gWrow);        // w codes k 0..15
    uint4 wc1 = *(const uint4*)(gWrow + 16);   // w codes k 16..31
    {
        uint4 ra = *(const uint4*)(gArow);
        *(uint4*)sAst = ra;
    }
    __syncthreads();

    for (int t = 0; t < NT; t++) {
        // Prefetch tile t+1 (clamped on last iter; store goes to the idle buffer).
        const int tn = (t + 1 < NT) ? (t + 1) : t;
        const int kn = tn * KT;
        uint4 ra_n = *(const uint4*)(gArow + kn);
        uint4 wn0  = *(const uint4*)(gWrow + kn);
        uint4 wn1  = *(const uint4*)(gWrow + kn + 16);

        const uint8_t* sAbuf = sArow + (t & 1) * SA_BUF;

        // Compute tile t: 16 m-rows x 32 k. A codes via broadcast LDS.64.
#pragma unroll
        for (int m = 0; m < 16; m++) {
            const uint8_t* ap = sAbuf + m * SA_STRIDE;
            uint2 a01 = *(const uint2*)(ap);        // k 0..7
            uint2 a23 = *(const uint2*)(ap + 8);    // k 8..15
            uint2 a45 = *(const uint2*)(ap + 16);   // k 16..23
            uint2 a67 = *(const uint2*)(ap + 24);   // k 24..31
            KGROUP8(a01.x, a01.y, wc0.x, wc0.y, acc[m]);
            KGROUP8(a23.x, a23.y, wc0.z, wc0.w, acc[m]);
            KGROUP8(a45.x, a45.y, wc1.x, wc1.y, acc[m]);
            KGROUP8(a67.x, a67.y, wc1.z, wc1.w, acc[m]);
        }

        // Stage tile t+1 into the other buffer, then sync.
        *(uint4*)(sAst + ((t + 1) & 1) * SA_BUF) = ra_n;
        __syncthreads();

        wc0 = wn0;
        wc1 = wn1;
    }

    const float b = bias[nLane];
#pragma unroll
    for (int m = 0; m < 16; m++) {
        out[(size_t)(m0 + mBase + m) * N_DIM + nLane] = (float)acc[m] + b;
    }
}

extern "C" void kernel_launch(void* const* d_in, const int* in_sizes, int n_in,
                              void* d_out, int out_size) {
    const float* input  = (const float*)d_in[0];  // [M, K] codes as f32
    const float* weight = (const float*)d_in[1];  // [N, K] codes as f32
    const float* bias   = (const float*)d_in[2];  // [N]
    const int*   lut    = (const int*)d_in[3];    // [256*256]
    float* out = (float*)d_out;

    (void)in_sizes; (void)n_in; (void)out_size;

    // Opt-in to >48KB dynamic smem (idempotent; capture-safe)
    cudaFuncSetAttribute((const void*)lut_gemm_kernel,
                         cudaFuncAttributeMaxDynamicSharedMemorySize, SMEM_BYTES);

    quantA_kernel<<<(M_DIM * K_DIM / 4 + 255) / 256, 256>>>(input);
    quantW_kernel<<<(N_DIM * K_DIM / 4 + 255) / 256, 256>>>(weight);
    quantLUT_kernel<<<(65536 / 4 + 255) / 256, 256>>>(lut);

    dim3 grid(1024);  // 16 x 64 tiles of 64 x 32
    lut_gemm_kernel<<<grid, 128, SMEM_BYTES>>>(bias, out);
}

// round 7
// speedup vs baseline: 1.0541x; 1.0398x over previous
#include <cuda_runtime.h>
#include <stdint.h>

// Problem shape (fixed by the dataset)
#define M_DIM 1024
#define K_DIM 2048
#define N_DIM 2048

// Tiling: 64 x 32 output tile per CTA, 128 threads (4 warps).
// Each warp: 16 m-rows x 32 n-lanes, acc[16] per thread.
// KT=32 k-slice; A and W tiles double-buffered in smem.
#define BM 64
#define BN 32
#define KT 32
#define NT (K_DIM / KT)        // 64 k-tiles

#define SA_STRIDE 32           // dense: broadcast reads don't conflict
#define SA_BUF (BM * SA_STRIDE)          // 2048 B
#define SW_STRIDE 80           // 16B-aligned, 80/16=5 odd -> LDS.128 4-phase min
#define SW_BUF (BN * SW_STRIDE)          // 2560 B

#define SMEM_BYTES (65536 + 2 * SA_BUF + 2 * SW_BUF)   // 74752 -> occ 3

// Scratch: quantized codes (allocation-free __device__ globals)
__device__ uint8_t g_A8[M_DIM * K_DIM];
__device__ uint8_t g_W8[N_DIM * K_DIM];
__device__ uint8_t g_LUT8[65536];

static __device__ __forceinline__ uint8_t clamp_u8(float v) {
    int c = (int)v;
    c = c < 0 ? 0 : (c > 255 ? 255 : c);
    return (uint8_t)c;
}

__global__ void quantA_kernel(const float* __restrict__ src) {
    int i = blockIdx.x * blockDim.x + threadIdx.x;   // groups of 4
    if (i < M_DIM * K_DIM / 4) {
        float4 v = ((const float4*)src)[i];
        uchar4 b;
        b.x = clamp_u8(v.x); b.y = clamp_u8(v.y);
        b.z = clamp_u8(v.z); b.w = clamp_u8(v.w);
        ((uchar4*)g_A8)[i] = b;
    }
}

__global__ void quantW_kernel(const float* __restrict__ src) {
    int i = blockIdx.x * blockDim.x + threadIdx.x;
    if (i < N_DIM * K_DIM / 4) {
        float4 v = ((const float4*)src)[i];
        uchar4 b;
        b.x = clamp_u8(v.x); b.y = clamp_u8(v.y);
        b.z = clamp_u8(v.z); b.w = clamp_u8(v.w);
        ((uchar4*)g_W8)[i] = b;
    }
}

__global__ void quantLUT_kernel(const int* __restrict__ lut) {
    int i = blockIdx.x * blockDim.x + threadIdx.x;   // groups of 4
    if (i < 65536 / 4) {
        int4 v = ((const int4*)lut)[i];
        uchar4 b;
        b.x = (uint8_t)v.x; b.y = (uint8_t)v.y;
        b.z = (uint8_t)v.z; b.w = (uint8_t)v.w;
        ((uchar4*)g_LUT8)[i] = b;
    }
}

// Index build: ((aword shift)&0xFF00)|w  -> SHF+LOP3 per index.
#define GATHER4(accv, aword, wv0, wv1, wv2, wv3)             \
    do {                                                     \
        uint32_t _i0 = (((aword) << 8)  & 0xFF00u) | (wv0);  \
        uint32_t _i1 = (( aword)        & 0xFF00u) | (wv1);  \
        uint32_t _i2 = (((aword) >> 8)  & 0xFF00u) | (wv2);  \
        uint32_t _i3 = (((aword) >> 16) & 0xFF00u) | (wv3);  \
        accv += sLUT[_i0];                                   \
        accv += sLUT[_i1];                                   \
        accv += sLUT[_i2];                                   \
        accv += sLUT[_i3];                                   \
    } while (0)

// One k-group of 8: a codes from two broadcast words, w codes from two words.
#define KGROUP8(alo, ahi, wlo, whi, accv)                                  \
    do {                                                                   \
        uint32_t _w0 =  (wlo)        & 255u, _w1 = ((wlo) >> 8)  & 255u;   \
        uint32_t _w2 = ((wlo) >> 16) & 255u, _w3 =  (wlo) >> 24;           \
        uint32_t _w4 =  (whi)        & 255u, _w5 = ((whi) >> 8)  & 255u;   \
        uint32_t _w6 = ((whi) >> 16) & 255u, _w7 =  (whi) >> 24;           \
        GATHER4(accv, alo, _w0, _w1, _w2, _w3);                            \
        GATHER4(accv, ahi, _w4, _w5, _w6, _w7);                            \
    } while (0)

// Main LUT-GEMM kernel.
// Grid: 1024 CTAs (16 m-tiles x 64 n-tiles), 128 threads, occ 3 -> 12 warps/SM.
__global__ void __launch_bounds__(128, 3)
lut_gemm_kernel(const float* __restrict__ bias,
                float* __restrict__ out) {
    extern __shared__ uint8_t smem[];
    uint8_t* sLUT = smem;                     // 65536 B
    uint8_t* sA   = smem + 65536;             // [2][BM][SA_STRIDE]
    uint8_t* sW   = sA + 2 * SA_BUF;          // [2][BN][SW_STRIDE]

    const int tid  = threadIdx.x;
    const int lane = tid & 31;
    const int warp = tid >> 5;                // 0..3 -> m-group of 16 rows

    // Copy pre-quantized LUT (64KB) into shared with 16B vector loads.
    for (int i = tid; i < 65536 / 16; i += 128) {
        ((uint4*)sLUT)[i] = ((const uint4*)g_LUT8)[i];
    }

    const int tileId = blockIdx.x;
    const int m0 = (tileId >> 6) * BM;        // 16 tile rows
    const int n0 = (tileId & 63) * BN;        // 64 tile cols

    const int mBase = warp * 16;              // warp's first row within tile
    const int nLane = n0 + lane;              // this lane's output column

    int acc[16];
#pragma unroll
    for (int i = 0; i < 16; i++) acc[i] = 0;

    // A staging: 128 threads cover 64 rows x 2 chunks of 16B. Dense layout:
    // STS addr = tid*16 (perfectly sequential).
    const int arow   = tid >> 1;
    const int achunk = (tid & 1) * 16;
    const uint8_t* gAst = g_A8 + ((size_t)(m0 + arow)) * K_DIM + achunk;
    uint8_t*       sAst = sA + arow * SA_STRIDE + achunk;

    // W staging: threads 0..63 cover 32 rows x 2 chunks of 16B (coalesced LDG,
    // 16B-aligned STS thanks to SW_STRIDE=80).
    const int wrow   = tid >> 1;              // valid for tid < 64
    const int wchunk = (tid & 1) * 16;
    const uint8_t* gWst = g_W8 + ((size_t)(n0 + wrow)) * K_DIM + wchunk;
    uint8_t*       sWst = sW + wrow * SW_STRIDE + wchunk;

    const uint8_t* sArow = sA + mBase * SA_STRIDE;
    const uint8_t* sWrow = sW + lane * SW_STRIDE;   // 16B-aligned per lane

    // ---- prologue: stage tile 0 into buffer 0 ----
    {
        uint4 ra = *(const uint4*)gAst;
        *(uint4*)sAst = ra;
        if (tid < 64) {
            uint4 rw = *(const uint4*)gWst;
            *(uint4*)sWst = rw;
        }
    }
    __syncthreads();

    for (int t = 0; t < NT; t++) {
        // Prefetch tile t+1 into registers (clamped on last iter).
        const int kn = ((t + 1 < NT) ? (t + 1) : t) * KT;
        uint4 ra_n = *(const uint4*)(gAst + kn);
        uint4 rw_n;
        if (tid < 64) rw_n = *(const uint4*)(gWst + kn);

        const int bufo = (t & 1);
        const uint8_t* sAbuf = sArow + bufo * SA_BUF;
        const uint8_t* sWbuf = sWrow + bufo * SW_BUF;

        // Per-lane w codes for this 32-k slice: 2x LDS.128 (4 wf each, min).
        uint4 wv0 = *(const uint4*)(sWbuf);        // k 0..15
        uint4 wv1 = *(const uint4*)(sWbuf + 16);   // k 16..31

        // Compute tile t: 16 m-rows x 32 k. A codes via broadcast LDS.64.
#pragma unroll
        for (int m = 0; m < 16; m++) {
            const uint8_t* ap = sAbuf + m * SA_STRIDE;
            uint2 a01 = *(const uint2*)(ap);        // k 0..7
            uint2 a23 = *(const uint2*)(ap + 8);    // k 8..15
            uint2 a45 = *(const uint2*)(ap + 16);   // k 16..23
            uint2 a67 = *(const uint2*)(ap + 24);   // k 24..31
            KGROUP8(a01.x, a01.y, wv0.x, wv0.y, acc[m]);
            KGROUP8(a23.x, a23.y, wv0.z, wv0.w, acc[m]);
            KGROUP8(a45.x, a45.y, wv1.x, wv1.y, acc[m]);
            KGROUP8(a67.x, a67.y, wv1.z, wv1.w, acc[m]);
        }

        // Stage tile t+1 into the other buffer, then sync.
        const int nbufo = ((t + 1) & 1);
        *(uint4*)(sAst + nbufo * SA_BUF) = ra_n;
        if (tid < 64) *(uint4*)(sWst + nbufo * SW_BUF) = rw_n;
        __syncthreads();
    }

    const float b = bias[nLane];
#pragma unroll
    for (int m = 0; m < 16; m++) {
        out[(size_t)(m0 + mBase + m) * N_DIM + nLane] = (float)acc[m] + b;
    }
}

extern "C" void kernel_launch(void* const* d_in, const int* in_sizes, int n_in,
                              void* d_out, int out_size) {
    const float* input  = (const float*)d_in[0];  // [M, K] codes as f32
    const float* weight = (const float*)d_in[1];  // [N, K] codes as f32
    const float* bias   = (const float*)d_in[2];  // [N]
    const int*   lut    = (const int*)d_in[3];    // [256*256]
    float* out = (float*)d_out;

    (void)in_sizes; (void)n_in; (void)out_size;

    // Opt-in to >48KB dynamic smem (idempotent; capture-safe)
    cudaFuncSetAttribute((const void*)lut_gemm_kernel,
                         cudaFuncAttributeMaxDynamicSharedMemorySize, SMEM_BYTES);

    quantA_kernel<<<(M_DIM * K_DIM / 4 + 255) / 256, 256>>>(input);
    quantW_kernel<<<(N_DIM * K_DIM / 4 + 255) / 256, 256>>>(weight);
    quantLUT_kernel<<<(65536 / 4 + 255) / 256, 256>>>(lut);

    dim3 grid(1024);  // 16 x 64 tiles of 64 x 32
    lut_gemm_kernel<<<grid, 128, SMEM_BYTES>>>(bias, out);
}